// round 2
// baseline (speedup 1.0000x reference)
#include <cuda_runtime.h>

// SymmetryConstraint: closed-form per-class moment reduction.
// loss = sum_b sum_{k in 0..2} [(m-2)*Su2 + Su^2 + m*Sy2 - Sy^2] / max(total_pairs, 1)
// where u = x - 0.5, moments accumulated over points of class k in batch b.

#define BATCH 256
#define NPTS  512
#define THREADS 256

__device__ float g_loss[BATCH];
__device__ float g_cnt[BATCH];
__device__ unsigned int g_done = 0;

__global__ __launch_bounds__(THREADS)
void symmetry_kernel(const float* __restrict__ kp,
                     const int* __restrict__ cls,
                     float* __restrict__ out)
{
    const int b   = blockIdx.x;
    const int tid = threadIdx.x;
    const int lane = tid & 31;
    const int wid  = tid >> 5;

    // 3 classes x {m, Su, Su2, Sy, Sy2}
    float acc[15];
#pragma unroll
    for (int i = 0; i < 15; i++) acc[i] = 0.f;

    const float2* kp2 = reinterpret_cast<const float2*>(kp) + (size_t)b * NPTS;
    const int*    c   = cls + (size_t)b * NPTS;

#pragma unroll
    for (int it = 0; it < NPTS / THREADS; it++) {
        int i = tid + it * THREADS;
        float2 p = kp2[i];
        int ci = c[i];
        float u = p.x - 0.5f;
        float y = p.y;
#pragma unroll
        for (int k = 0; k < 3; k++) {
            float w = (ci == k) ? 1.f : 0.f;
            acc[k * 5 + 0] += w;
            acc[k * 5 + 1] += w * u;
            acc[k * 5 + 2] += w * u * u;
            acc[k * 5 + 3] += w * y;
            acc[k * 5 + 4] += w * y * y;
        }
    }

    // warp reduce all 15
#pragma unroll
    for (int i = 0; i < 15; i++) {
#pragma unroll
        for (int off = 16; off; off >>= 1)
            acc[i] += __shfl_down_sync(0xffffffffu, acc[i], off);
    }

    __shared__ float smem[THREADS / 32][15];
    __shared__ float s_flag;
    if (lane == 0) {
#pragma unroll
        for (int i = 0; i < 15; i++) smem[wid][i] = acc[i];
    }
    __syncthreads();

    if (tid == 0) {
        float tot[15];
#pragma unroll
        for (int i = 0; i < 15; i++) {
            float s = 0.f;
#pragma unroll
            for (int w = 0; w < THREADS / 32; w++) s += smem[w][i];
            tot[i] = s;
        }
        float loss = 0.f, cnt = 0.f;
#pragma unroll
        for (int k = 0; k < 3; k++) {
            float m   = tot[k * 5 + 0];
            float su  = tot[k * 5 + 1];
            float su2 = tot[k * 5 + 2];
            float sy  = tot[k * 5 + 3];
            float sy2 = tot[k * 5 + 4];
            loss += (m - 2.f) * su2 + su * su + m * sy2 - sy * sy;
            cnt  += 0.5f * m * (m - 1.f);
        }
        g_loss[b] = loss;
        g_cnt[b]  = cnt;
        __threadfence();
        unsigned int prev = atomicAdd(&g_done, 1u);
        s_flag = (prev == BATCH - 1) ? 1.f : 0.f;
    }
    __syncthreads();

    if (s_flag != 0.f) {
        // last block: deterministic final reduce over 256 per-batch entries
        float l  = g_loss[tid];
        float cn = g_cnt[tid];
#pragma unroll
        for (int off = 16; off; off >>= 1) {
            l  += __shfl_down_sync(0xffffffffu, l,  off);
            cn += __shfl_down_sync(0xffffffffu, cn, off);
        }
        __shared__ float sl[THREADS / 32], sc[THREADS / 32];
        if (lane == 0) { sl[wid] = l; sc[wid] = cn; }
        __syncthreads();
        if (tid == 0) {
            float L = 0.f, C = 0.f;
#pragma unroll
            for (int w = 0; w < THREADS / 32; w++) { L += sl[w]; C += sc[w]; }
            out[0] = L / fmaxf(C, 1.f);
            g_done = 0u;  // reset for next graph replay
        }
    }
}

extern "C" void kernel_launch(void* const* d_in, const int* in_sizes, int n_in,
                              void* d_out, int out_size)
{
    const float* kp  = (const float*)d_in[0];   // [256, 512, 2] f32
    const int*   cls = (const int*)d_in[1];     // [256, 512] i32
    float*       out = (float*)d_out;           // [1] f32
    symmetry_kernel<<<BATCH, THREADS>>>(kp, cls, out);
}

// round 4
// speedup vs baseline: 1.0149x; 1.0149x over previous
#include <cuda_runtime.h>

// SymmetryConstraint: closed-form per-class moment reduction + deterministic
// fixed-point integer REDG accumulation across batches.
//
// Per (batch b, class k in {0,1,2}) with m points, u = x-0.5:
//   pair-loss sum = (m-2)*Su2 + Su^2 + m*Sy2 - Sy^2   (>= 0, exactly 0 for m<=1)
//   pair count    = m(m-1)/2
// result = total_loss / max(total_count, 1)

#define BATCH   256
#define NPTS    512
#define THREADS 128

__device__ unsigned long long g_loss_fix = 0ULL;
__device__ unsigned long long g_cnt_fix  = 0ULL;
__device__ unsigned int       g_done     = 0u;

#define LOSS_SCALE 33554432.0f   // 2^25

__global__ __launch_bounds__(THREADS)
void symmetry_kernel(const float4* __restrict__ kp4,
                     const int2*   __restrict__ cls2,
                     float* __restrict__ out)
{
    const int b    = blockIdx.x;
    const int tid  = threadIdx.x;
    const int lane = tid & 31;
    const int wid  = tid >> 5;

    // Each float4 = 2 points (x0,y0,x1,y1); 512 pts = 256 float4 per batch.
    // Thread tid handles float4 slots {tid, tid+128} -> 4 points, with
    // matching int2 class slots {tid, tid+128}.
    const float4* kb = kp4  + (size_t)b * (NPTS / 2);
    const int2*   cb = cls2 + (size_t)b * (NPTS / 2);

    float4 p0 = kb[tid];
    float4 p1 = kb[tid + THREADS];
    int2   c0 = cb[tid];
    int2   c1 = cb[tid + THREADS];

    // 3 classes x {m, Su, Su2, Sy, Sy2}
    float acc[15];
#pragma unroll
    for (int i = 0; i < 15; i++) acc[i] = 0.f;

    float px[4] = { p0.x, p0.z, p1.x, p1.z };
    float py[4] = { p0.y, p0.w, p1.y, p1.w };
    int   pc[4] = { c0.x, c0.y, c1.x, c1.y };

#pragma unroll
    for (int j = 0; j < 4; j++) {
        float u = px[j] - 0.5f;
        float y = py[j];
        int   ci = pc[j];
#pragma unroll
        for (int k = 0; k < 3; k++) {
            float w = (ci == k) ? 1.f : 0.f;
            acc[k * 5 + 0] += w;
            acc[k * 5 + 1] += w * u;
            acc[k * 5 + 2] += w * u * u;
            acc[k * 5 + 3] += w * y;
            acc[k * 5 + 4] += w * y * y;
        }
    }

    // warp reduce 15 independent values
#pragma unroll
    for (int i = 0; i < 15; i++) {
#pragma unroll
        for (int off = 16; off; off >>= 1)
            acc[i] += __shfl_down_sync(0xffffffffu, acc[i], off);
    }

    __shared__ float smem[THREADS / 32][15];
    if (lane == 0) {
#pragma unroll
        for (int i = 0; i < 15; i++) smem[wid][i] = acc[i];
    }
    __syncthreads();

    if (tid == 0) {
        float loss = 0.f, cnt = 0.f;
#pragma unroll
        for (int k = 0; k < 3; k++) {
            float m = 0.f, su = 0.f, su2 = 0.f, sy = 0.f, sy2 = 0.f;
#pragma unroll
            for (int w = 0; w < THREADS / 32; w++) {
                m   += smem[w][k * 5 + 0];
                su  += smem[w][k * 5 + 1];
                su2 += smem[w][k * 5 + 2];
                sy  += smem[w][k * 5 + 3];
                sy2 += smem[w][k * 5 + 4];
            }
            loss += (m - 2.f) * su2 + su * su + m * sy2 - sy * sy;
            cnt  += 0.5f * m * (m - 1.f);   // exact: m integer-valued < 2^12
        }
        // loss >= 0 mathematically; clamp tiny negative rounding residue
        loss = fmaxf(loss, 0.f);

        // deterministic integer accumulation (REDG, order-independent)
        unsigned long long lfix = (unsigned long long)(loss * LOSS_SCALE + 0.5f);
        unsigned long long cfix = (unsigned long long)(cnt + 0.5f);
        atomicAdd(&g_loss_fix, lfix);
        atomicAdd(&g_cnt_fix,  cfix);
        __threadfence();

        if (atomicAdd(&g_done, 1u) == BATCH - 1) {
            // last block: all REDGs are globally visible (fence before counter)
            unsigned long long L = atomicAdd(&g_loss_fix, 0ULL);
            unsigned long long C = atomicAdd(&g_cnt_fix,  0ULL);
            double total = (double)L * (1.0 / 33554432.0);
            double denom = (C > 0ULL) ? (double)C : 1.0;
            out[0] = (float)(total / denom);
            // reset for next graph replay (ordered by kernel completion)
            g_loss_fix = 0ULL;
            g_cnt_fix  = 0ULL;
            g_done     = 0u;
            __threadfence();
        }
    }
}

extern "C" void kernel_launch(void* const* d_in, const int* in_sizes, int n_in,
                              void* d_out, int out_size)
{
    const float4* kp4  = (const float4*)d_in[0];  // [256, 512, 2] f32
    const int2*   cls2 = (const int2*)d_in[1];    // [256, 512] i32
    float*        out  = (float*)d_out;           // [1] f32
    symmetry_kernel<<<BATCH, THREADS>>>(kp4, cls2, out);
}